// round 17
// baseline (speedup 1.0000x reference)
#include <cuda_runtime.h>
#include <cuda_fp16.h>
#include <math.h>
#include <stdint.h>

// Problem constants
#define S_LEN  2048
#define HDIM   4096
#define NHEADS 32
#define HEADD  128
#define KSEG   4096

// Scratch (device globals) — all-fp16 dataflow
__device__ __half g_Xf[S_LEN * KSEG];           // X fp16 / attn out fp16
__device__ __half g_Qh[S_LEN * HDIM];           // Q proj fp16 [s][4096]
__device__ __half g_Kh[S_LEN * HDIM];
__device__ __half g_Wqf[HDIM * KSEG];           // plain fp16 weights
__device__ __half g_Wkf[HDIM * KSEG];
__device__ __half g_Wvf[HDIM * KSEG];
__device__ __half g_Wof[HDIM * KSEG];
__device__ __half g_Q2f[NHEADS * S_LEN * HEADD]; // rope'd, scaled [h][s][128]
__device__ __half g_K2f[NHEADS * S_LEN * HEADD]; // rope'd [h][s][128]
__device__ __half g_Vf[NHEADS * S_LEN * HEADD];  // [h][s][128]

// ===========================================================================
// PTX helpers
// ===========================================================================
__device__ __forceinline__ uint32_t smem_u32(const void* p) {
    uint32_t a;
    asm("{ .reg .u64 t; cvta.to.shared.u64 t, %1; cvt.u32.u64 %0, t; }" : "=r"(a) : "l"(p));
    return a;
}
__device__ __forceinline__ void cp_async16(uint32_t dst, const void* src) {
    asm volatile("cp.async.cg.shared.global [%0], [%1], 16;" :: "r"(dst), "l"(src));
}
__device__ __forceinline__ void cp_commit() {
    asm volatile("cp.async.commit_group;" ::: "memory");
}
template <int N> __device__ __forceinline__ void cp_wait() {
    asm volatile("cp.async.wait_group %0;" :: "n"(N) : "memory");
}
__device__ __forceinline__ void ldsm_x4(uint32_t& r0, uint32_t& r1, uint32_t& r2,
                                        uint32_t& r3, uint32_t addr) {
    asm volatile("ldmatrix.sync.aligned.m8n8.x4.shared.b16 {%0,%1,%2,%3}, [%4];"
                 : "=r"(r0), "=r"(r1), "=r"(r2), "=r"(r3) : "r"(addr));
}
__device__ __forceinline__ void ldsm_x4t(uint32_t& r0, uint32_t& r1, uint32_t& r2,
                                         uint32_t& r3, uint32_t addr) {
    asm volatile("ldmatrix.sync.aligned.m8n8.x4.trans.shared.b16 {%0,%1,%2,%3}, [%4];"
                 : "=r"(r0), "=r"(r1), "=r"(r2), "=r"(r3) : "r"(addr));
}
__device__ __forceinline__ void mma16816f(float* c, const uint32_t* a, const uint32_t* b) {
    asm volatile(
        "mma.sync.aligned.m16n8k16.row.col.f32.f16.f16.f32 "
        "{%0,%1,%2,%3}, {%4,%5,%6,%7}, {%8,%9}, {%0,%1,%2,%3};"
        : "+f"(c[0]), "+f"(c[1]), "+f"(c[2]), "+f"(c[3])
        : "r"(a[0]), "r"(a[1]), "r"(a[2]), "r"(a[3]), "r"(b[0]), "r"(b[1]));
}

__device__ __forceinline__ uint32_t pkh(__half a, __half b) {
    __half2 t = __halves2half2(a, b);
    return *reinterpret_cast<uint32_t*>(&t);
}

// ===========================================================================
// Convert kernels (MLP=2: two float4 per thread)
// ===========================================================================
__global__ void __launch_bounds__(256) conv_f16(const float* __restrict__ src,
                                                __half* __restrict__ dst,
                                                int total4)
{
    int i0 = blockIdx.x * 512 + threadIdx.x;
    int i1 = i0 + 256;
    float4 v0 = ((const float4*)src)[i0];
    float4 v1 = (i1 < total4) ? ((const float4*)src)[i1]
                              : make_float4(0.f, 0.f, 0.f, 0.f);
    *(uint2*)(dst + (size_t)i0 * 4) =
        make_uint2(pkh(__float2half_rn(v0.x), __float2half_rn(v0.y)),
                   pkh(__float2half_rn(v0.z), __float2half_rn(v0.w)));
    if (i1 < total4)
        *(uint2*)(dst + (size_t)i1 * 4) =
            make_uint2(pkh(__float2half_rn(v1.x), __float2half_rn(v1.y)),
                       pkh(__float2half_rn(v1.z), __float2half_rn(v1.w)));
}

// ===========================================================================
// GEMM common: CTA 128x128, BK=32, 128 threads (2x2 warps, 64x64/warp),
// 4-stage cp.async, 2 CTAs/SM. Plain fp16, K=4096 (128 iters).
// ===========================================================================
#define BM 128
#define BN 128
#define BK 32
#define NITERP  128
#define GSTAGES 4
#define ROWB    80
#define ASZ     (BM * ROWB)
#define STAGE   (2 * ASZ)
#define GSMEM   (GSTAGES * STAGE)

__device__ __forceinline__ void g_load_stage_p(uint32_t sb,
                                               const __half* __restrict__ A2,
                                               const __half* __restrict__ B2,
                                               int m0, int n0, int j, int t)
{
    const int kloc = j * BK;
#pragma unroll
    for (int i = 0; i < 4; ++i) {
        int c   = t + (i << 7);
        int row = c >> 2;
        int kc  = c & 3;
        cp_async16(sb + row * ROWB + kc * 16,
                   A2 + (size_t)(m0 + row) * KSEG + kloc + kc * 8);
    }
#pragma unroll
    for (int i = 0; i < 4; ++i) {
        int c   = t + (i << 7);
        int row = c >> 2;
        int kc  = c & 3;
        cp_async16(sb + ASZ + row * ROWB + kc * 16,
                   B2 + (size_t)(n0 + row) * KSEG + kloc + kc * 8);
    }
    cp_commit();
}

#define GEMM_BODY_P(APTR, BPTR)                                               \
    float acc[4][8][4];                                                       \
    _Pragma("unroll")                                                         \
    for (int mi = 0; mi < 4; ++mi)                                            \
        _Pragma("unroll")                                                     \
        for (int nj = 0; nj < 8; ++nj)                                        \
            _Pragma("unroll")                                                 \
            for (int q = 0; q < 4; ++q) acc[mi][nj][q] = 0.0f;                \
    _Pragma("unroll")                                                         \
    for (int it = 0; it < GSTAGES - 1; ++it)                                  \
        g_load_stage_p(base + it * STAGE, APTR, BPTR, m0, n0, it, t);         \
    for (int it = 0; it < NITERP; ++it) {                                     \
        const int st = it & (GSTAGES - 1);                                    \
        cp_wait<GSTAGES - 2>();                                               \
        __syncthreads();                                                      \
        const uint32_t stA = base + st * STAGE;                               \
        const uint32_t stB = stA + ASZ;                                       \
        _Pragma("unroll")                                                     \
        for (int kh = 0; kh < 2; ++kh) {                                      \
            uint32_t a[4][4];                                                 \
            _Pragma("unroll")                                                 \
            for (int mi = 0; mi < 4; ++mi)                                    \
                ldsm_x4(a[mi][0], a[mi][1], a[mi][2], a[mi][3],               \
                        stA + (uint32_t)((wm + mi * 16 + rA) * ROWB           \
                                         + (kh * 2 + selA) * 16));            \
            uint32_t b[4][4];                                                 \
            _Pragma("unroll")                                                 \
            for (int p = 0; p < 4; ++p)                                       \
                ldsm_x4(b[p][0], b[p][1], b[p][2], b[p][3],                   \
                        stB + (uint32_t)((wn + p * 16 + rB) * ROWB            \
                                         + (kh * 2 + selB) * 16));            \
            _Pragma("unroll")                                                 \
            for (int mi = 0; mi < 4; ++mi) {                                  \
                _Pragma("unroll")                                             \
                for (int p = 0; p < 4; ++p) {                                 \
                    mma16816f(acc[mi][2 * p],     a[mi], &b[p][0]);           \
                    mma16816f(acc[mi][2 * p + 1], a[mi], &b[p][2]);           \
                }                                                             \
            }                                                                 \
        }                                                                     \
        const int j = it + GSTAGES - 1;                                       \
        if (j < NITERP)                                                       \
            g_load_stage_p(base + (j & (GSTAGES - 1)) * STAGE, APTR, BPTR,    \
                           m0, n0, j, t);                                     \
    }

#define GEMM_PROLOG_COMMON                                                    \
    extern __shared__ char smraw[];                                           \
    const uint32_t base = smem_u32(smraw);                                    \
    const int t    = threadIdx.x;                                             \
    const int wid  = t >> 5;                                                  \
    const int lane = t & 31;                                                  \
    const int m0   = blockIdx.y * BM;                                         \
    const int wm   = (wid >> 1) * 64;                                         \
    const int wn   = (wid & 1) * 64;                                          \
    const int rA   = lane & 15;                                               \
    const int selA = lane >> 4;                                               \
    const int rB   = ((lane >> 4) << 3) | (lane & 7);                         \
    const int selB = (lane >> 3) & 1;

// Merged Q+K+V projection: grid.x covers 3*HDIM; all outputs fp16.
__global__ void __launch_bounds__(128, 2)
gemm_qkv(const __half* __restrict__ A2,
         const __half* __restrict__ Bq,
         const __half* __restrict__ Bk,
         const __half* __restrict__ Bv,
         __half* __restrict__ Qh,
         __half* __restrict__ Kh,
         __half* __restrict__ Vf)
{
    GEMM_PROLOG_COMMON
    const int n0g = blockIdx.x * BN;
    const int n0  = n0g & (HDIM - 1);
    const __half* B2 = (n0g < HDIM) ? Bq : ((n0g < 2 * HDIM) ? Bk : Bv);
    const int er = lane >> 2;
    const int ec = (lane & 3) << 1;

    GEMM_BODY_P(A2, B2)

    if (n0g < 2 * HDIM) {
        __half* Cf = (n0g < HDIM) ? Qh : Kh;
#pragma unroll
        for (int mi = 0; mi < 4; ++mi) {
#pragma unroll
            for (int nj = 0; nj < 8; ++nj) {
                size_t r0 = (size_t)(m0 + wm + mi * 16 + er) * HDIM
                            + (n0 + wn + nj * 8 + ec);
                *(uint32_t*)(Cf + r0) = pkh(__float2half_rn(acc[mi][nj][0]),
                                            __float2half_rn(acc[mi][nj][1]));
                *(uint32_t*)(Cf + r0 + 8 * HDIM) =
                    pkh(__float2half_rn(acc[mi][nj][2]),
                        __float2half_rn(acc[mi][nj][3]));
            }
        }
    } else {
#pragma unroll
        for (int mi = 0; mi < 4; ++mi) {
            int s0 = m0 + wm + mi * 16 + er;
#pragma unroll
            for (int nj = 0; nj < 8; ++nj) {
                int col = n0 + wn + nj * 8 + ec;
                int h   = col >> 7;
                int hc  = col & 127;
                size_t b0 = ((size_t)h * S_LEN + s0) * HEADD + hc;
                size_t b1 = ((size_t)h * S_LEN + s0 + 8) * HEADD + hc;
                *(uint32_t*)(Vf + b0) = pkh(__float2half_rn(acc[mi][nj][0]),
                                            __float2half_rn(acc[mi][nj][1]));
                *(uint32_t*)(Vf + b1) = pkh(__float2half_rn(acc[mi][nj][2]),
                                            __float2half_rn(acc[mi][nj][3]));
            }
        }
    }
}

// Plain fp16 GEMM, fp32 output (O projection)
__global__ void __launch_bounds__(128, 2)
gemm_f16o(const __half* __restrict__ A2,
          const __half* __restrict__ B2,
          float* __restrict__ C)
{
    GEMM_PROLOG_COMMON
    const int n0 = blockIdx.x * BN;
    GEMM_BODY_P(A2, B2)

    const int er = lane >> 2;
    const int ec = (lane & 3) << 1;
#pragma unroll
    for (int mi = 0; mi < 4; ++mi) {
#pragma unroll
        for (int nj = 0; nj < 8; ++nj) {
            size_t r0 = (size_t)(m0 + wm + mi * 16 + er) * HDIM
                        + (n0 + wn + nj * 8 + ec);
            *(float2*)&C[r0]            = make_float2(acc[mi][nj][0], acc[mi][nj][1]);
            *(float2*)&C[r0 + 8 * HDIM] = make_float2(acc[mi][nj][2], acc[mi][nj][3]);
        }
    }
}

// ===========================================================================
// RoPE fp16 -> fp16, per-head layout: Q2f[h][s][128] (scaled), K2f[h][s][128]
// ===========================================================================
#define ATT_SCALE 0.08838834764831843f

__global__ void __launch_bounds__(256) rope_f16(
    const __half* __restrict__ Qh, const __half* __restrict__ Kh,
    const int* __restrict__ pos,
    __half* __restrict__ Q2, __half* __restrict__ K2o)
{
    int idx = blockIdx.x * 256 + threadIdx.x;        // S*NH*16
    if (idx >= S_LEN * NHEADS * 16) return;
    int j4 = (idx & 15) << 2;
    int h  = (idx >> 4) & (NHEADS - 1);
    int s  = idx >> 9;
    int p  = pos[s];

    float sn[4], cs[4];
#pragma unroll
    for (int i = 0; i < 4; ++i) {
        float inv = 1.0f / powf(10000.0f, (float)(j4 + i) * (1.0f / 64.0f));
        sincosf((float)p * inv, &sn[i], &cs[i]);
    }

    size_t gb = (size_t)s * HDIM + (size_t)h * HEADD + j4;
    uint2 qa4 = *(const uint2*)(Qh + gb);
    uint2 qb4 = *(const uint2*)(Qh + gb + 64);
    uint2 ka4 = *(const uint2*)(Kh + gb);
    uint2 kb4 = *(const uint2*)(Kh + gb + 64);
    const __half* qa = (const __half*)&qa4;
    const __half* qb = (const __half*)&qb4;
    const __half* ka = (const __half*)&ka4;
    const __half* kb = (const __half*)&kb4;

    __half q1[4], q2[4], k1[4], k2[4];
#pragma unroll
    for (int i = 0; i < 4; ++i) {
        float qaf = __half2float(qa[i]), qbf = __half2float(qb[i]);
        float kaf = __half2float(ka[i]), kbf = __half2float(kb[i]);
        q1[i] = __float2half_rn((qaf * cs[i] - qbf * sn[i]) * ATT_SCALE);
        q2[i] = __float2half_rn((qbf * cs[i] + qaf * sn[i]) * ATT_SCALE);
        k1[i] = __float2half_rn(kaf * cs[i] - kbf * sn[i]);
        k2[i] = __float2half_rn(kbf * cs[i] + kaf * sn[i]);
    }

    size_t ob = ((size_t)h * S_LEN + s) * HEADD + j4;
    *(uint2*)(Q2 + ob)       = make_uint2(pkh(q1[0], q1[1]), pkh(q1[2], q1[3]));
    *(uint2*)(Q2 + ob + 64)  = make_uint2(pkh(q2[0], q2[1]), pkh(q2[2], q2[3]));
    *(uint2*)(K2o + ob)      = make_uint2(pkh(k1[0], k1[1]), pkh(k1[2], k1[3]));
    *(uint2*)(K2o + ob + 64) = make_uint2(pkh(k2[0], k2[1]), pkh(k2[2], k2[3]));
}

// ===========================================================================
// Flash attention v7: 256 threads, all-plain fp16.
// Scores: single-pass fp16 (K=128). fp32 softmax -> fp16 P. PV fp16 1-pass.
// Q/K/V rows all 128 fp16 (FROWV). K+V double-buffered.
// ===========================================================================
#define NEG_BIG (-3.0e38f)
#define FROWV  272    // 128 fp16 + 16B pad
#define FROWP  144    // 64 fp16 + pad
#define OFF_KS   (64 * FROWV)                         // after Q (17408)
#define OFF_VS   (OFF_KS + 2 * 64 * FROWV)            // 52224
#define OFF_SS   (OFF_VS + 2 * 64 * FROWV)            // 87040
#define OFF_PS   (OFF_SS + 64 * 68 * 4)               // 104448
#define OFF_RW   (OFF_PS + 64 * FROWP)                // 113664
#define FSMEM    (OFF_RW + 3 * 64 * 4)                // 114432

__device__ __forceinline__ void f_load_kv(uint32_t sb, int buf,
                                          const __half* __restrict__ Kg,
                                          const __half* __restrict__ Vg,
                                          int t)
{
    uint32_t kb = sb + OFF_KS + buf * (64 * FROWV);
    for (int c = t; c < 64 * 16; c += 256) {
        int r = c >> 4, ch = c & 15;
        cp_async16(kb + r * FROWV + ch * 16,
                   (const char*)Kg + (size_t)r * (HEADD * 2) + ch * 16);
    }
    uint32_t vb = sb + OFF_VS + buf * (64 * FROWV);
    for (int c = t; c < 64 * 16; c += 256) {
        int r = c >> 4, ch = c & 15;
        cp_async16(vb + r * FROWV + ch * 16,
                   (const char*)Vg + (size_t)r * (HEADD * 2) + ch * 16);
    }
    cp_commit();
}

__global__ void __launch_bounds__(256) flash2(
    const __half* __restrict__ Q2,
    const __half* __restrict__ K2g,
    const __half* __restrict__ Vf,
    __half* __restrict__ Aout)
{
    extern __shared__ char smraw[];
    const uint32_t sb = smem_u32(smraw);
    float* Ss  = (float*)(smraw + OFF_SS);
    __half* Ps = (__half*)(smraw + OFF_PS);
    float* mrow = (float*)(smraw + OFF_RW);
    float* lrow = mrow + 64;
    float* srow = lrow + 64;

    const int h  = blockIdx.x;
    const int qb = (gridDim.y - 1) - blockIdx.y;   // heavy blocks first
    const int q0 = qb * 64;
    const int t = threadIdx.x, wid = t >> 5, lane = t & 31;
    const int wm = (wid >> 2) * 32;
    const int wn = (wid & 3) * 16;
    const int wnv = (wid & 3) * 32;
    const int rA = lane & 15, selA = lane >> 4;
    const int rB = ((lane >> 4) << 3) | (lane & 7), selB = (lane >> 3) & 1;
    const int er = lane >> 2, ec = (lane & 3) << 1;

    // Q tile: 64 rows x 256B
    const __half* Qg = Q2 + ((size_t)h * S_LEN + q0) * HEADD;
    for (int c = t; c < 64 * 16; c += 256) {
        int r = c >> 4, ch = c & 15;
        cp_async16(sb + r * FROWV + ch * 16,
                   (const char*)Qg + (size_t)r * (HEADD * 2) + ch * 16);
    }
    cp_commit();
    if (t < 64) { mrow[t] = NEG_BIG; lrow[t] = 0.0f; }

    f_load_kv(sb, 0, K2g + ((size_t)h * S_LEN) * HEADD,
              Vf + ((size_t)h * S_LEN) * HEADD, t);

    float oacc[2][4][4];
#pragma unroll
    for (int mi = 0; mi < 2; ++mi)
#pragma unroll
        for (int nj = 0; nj < 4; ++nj)
#pragma unroll
            for (int q = 0; q < 4; ++q) oacc[mi][nj][q] = 0.0f;

    for (int kb = 0; kb <= qb; ++kb) {
        const int buf = kb & 1;
        cp_wait<0>();
        __syncthreads();

        if (kb + 1 <= qb)
            f_load_kv(sb, buf ^ 1,
                      K2g + ((size_t)h * S_LEN + (kb + 1) * 64) * HEADD,
                      Vf + ((size_t)h * S_LEN + (kb + 1) * 64) * HEADD, t);

        const uint32_t kbase = sb + OFF_KS + buf * (64 * FROWV);
        const uint32_t vbase = sb + OFF_VS + buf * (64 * FROWV);

        // ---- scores: single pass, K=128 ----
        float sacc[2][2][4];
#pragma unroll
        for (int mi = 0; mi < 2; ++mi)
#pragma unroll
            for (int nj = 0; nj < 2; ++nj)
#pragma unroll
                for (int q = 0; q < 4; ++q) sacc[mi][nj][q] = 0.0f;

#pragma unroll
        for (int k16 = 0; k16 < 8; ++k16) {
            uint32_t a[2][4], b[4];
#pragma unroll
            for (int mi = 0; mi < 2; ++mi)
                ldsm_x4(a[mi][0], a[mi][1], a[mi][2], a[mi][3],
                        sb + (uint32_t)((wm + mi * 16 + rA) * FROWV
                                        + k16 * 32 + selA * 16));
            ldsm_x4(b[0], b[1], b[2], b[3],
                    kbase + (uint32_t)((wn + rB) * FROWV + k16 * 32 + selB * 16));
#pragma unroll
            for (int mi = 0; mi < 2; ++mi)
#pragma unroll
                for (int nj = 0; nj < 2; ++nj)
                    mma16816f(sacc[mi][nj], a[mi], &b[nj << 1]);
        }

        const bool diag = (kb == qb);
#pragma unroll
        for (int mi = 0; mi < 2; ++mi) {
#pragma unroll
            for (int nj = 0; nj < 2; ++nj) {
                int row = wm + mi * 16 + er;
                int col = wn + nj * 8 + ec;
                float v0 = sacc[mi][nj][0], v1 = sacc[mi][nj][1];
                float v2 = sacc[mi][nj][2], v3 = sacc[mi][nj][3];
                if (diag) {
                    if (col > row)     v0 = NEG_BIG;
                    if (col + 1 > row) v1 = NEG_BIG;
                    if (col > row + 8)     v2 = NEG_BIG;
                    if (col + 1 > row + 8) v3 = NEG_BIG;
                }
                Ss[row * 68 + col]       = v0;
                Ss[row * 68 + col + 1]   = v1;
                Ss[(row + 8) * 68 + col]     = v2;
                Ss[(row + 8) * 68 + col + 1] = v3;
            }
        }
        __syncthreads();

        // ---- online softmax (fp32) -> fp16 P ----
        {
            int r  = t >> 2;
            int qd = t & 3;
            float* srw = &Ss[r * 68 + qd * 16];
            __half* prw = &Ps[r * 72 + qd * 16];
            float vals[16];
            float mx = NEG_BIG;
#pragma unroll
            for (int i = 0; i < 16; ++i) { vals[i] = srw[i]; mx = fmaxf(mx, vals[i]); }
            mx = fmaxf(mx, __shfl_xor_sync(0xffffffffu, mx, 1));
            mx = fmaxf(mx, __shfl_xor_sync(0xffffffffu, mx, 2));
            float mold = mrow[r];
            float mnew = fmaxf(mold, mx);
            float sum = 0.0f;
#pragma unroll
            for (int i = 0; i < 16; ++i) {
                float p = __expf(vals[i] - mnew);
                prw[i] = __float2half_rn(p);
                sum += p;
            }
            sum += __shfl_xor_sync(0xffffffffu, sum, 1);
            sum += __shfl_xor_sync(0xffffffffu, sum, 2);
            float corr = __expf(mold - mnew);
            if (qd == 0) {
                mrow[r] = mnew;
                lrow[r] = lrow[r] * corr + sum;
                srow[r] = corr;
            }
        }
        __syncthreads();

        // ---- rescale + PV: single-pass fp16 ----
#pragma unroll
        for (int mi = 0; mi < 2; ++mi) {
            float c0 = srow[wm + mi * 16 + er];
            float c1 = srow[wm + mi * 16 + er + 8];
#pragma unroll
            for (int nj = 0; nj < 4; ++nj) {
                oacc[mi][nj][0] *= c0; oacc[mi][nj][1] *= c0;
                oacc[mi][nj][2] *= c1; oacc[mi][nj][3] *= c1;
            }
        }

        const int vkr = ((lane >> 3) & 1) * 8 + (lane & 7);
        const int vnc = (lane >> 4) * 8;
#pragma unroll
        for (int kk = 0; kk < 4; ++kk) {
            uint32_t a[2][4], b0[4], b1[4];
#pragma unroll
            for (int mi = 0; mi < 2; ++mi)
                ldsm_x4(a[mi][0], a[mi][1], a[mi][2], a[mi][3],
                        sb + OFF_PS + (uint32_t)((wm + mi * 16 + rA) * FROWP)
                           + kk * 32 + selA * 16);
            uint32_t vaddr = vbase + (uint32_t)((kk * 16 + vkr) * FROWV);
            ldsm_x4t(b0[0], b0[1], b0[2], b0[3], vaddr + (wnv + vnc) * 2);
            ldsm_x4t(b1[0], b1[1], b1[2], b1[3], vaddr + (wnv + 16 + vnc) * 2);
#pragma unroll
            for (int mi = 0; mi < 2; ++mi) {
                mma16816f(oacc[mi][0], a[mi], &b0[0]);
                mma16816f(oacc[mi][1], a[mi], &b0[2]);
                mma16816f(oacc[mi][2], a[mi], &b1[0]);
                mma16816f(oacc[mi][3], a[mi], &b1[2]);
            }
        }
    }

    // epilogue: normalize, write plain fp16 to Aout [s][4096]
#pragma unroll
    for (int mi = 0; mi < 2; ++mi) {
        float l0 = 1.0f / lrow[wm + mi * 16 + er];
        float l1 = 1.0f / lrow[wm + mi * 16 + er + 8];
#pragma unroll
        for (int nj = 0; nj < 4; ++nj) {
            int col = h * HEADD + wnv + nj * 8 + ec;
            size_t r0 = (size_t)(q0 + wm + mi * 16 + er) * KSEG + col;
            size_t r1 = r0 + (size_t)8 * KSEG;
            *(uint32_t*)(Aout + r0) =
                pkh(__float2half_rn(oacc[mi][nj][0] * l0),
                    __float2half_rn(oacc[mi][nj][1] * l0));
            *(uint32_t*)(Aout + r1) =
                pkh(__float2half_rn(oacc[mi][nj][2] * l1),
                    __float2half_rn(oacc[mi][nj][3] * l1));
        }
    }
}

// ===========================================================================
// Launch
// ===========================================================================
extern "C" void kernel_launch(void* const* d_in, const int* in_sizes, int n_in,
                              void* d_out, int out_size)
{
    (void)in_sizes; (void)n_in; (void)out_size;

    const float* X   = (const float*)d_in[0];
    const int*   pos = (const int*)d_in[2];
    const float* Wq  = (const float*)d_in[3];
    const float* Wk  = (const float*)d_in[4];
    const float* Wv  = (const float*)d_in[5];
    const float* Wo  = (const float*)d_in[6];
    float* out = (float*)d_out;

    __half *Xfd, *Qhd, *Khd, *Wqfd, *Wkfd, *Wvfd, *Wofd, *Q2d, *K2d, *Vfd;
    cudaGetSymbolAddress((void**)&Xfd, g_Xf);
    cudaGetSymbolAddress((void**)&Qhd, g_Qh);
    cudaGetSymbolAddress((void**)&Khd, g_Kh);
    cudaGetSymbolAddress((void**)&Wqfd, g_Wqf);
    cudaGetSymbolAddress((void**)&Wkfd, g_Wkf);
    cudaGetSymbolAddress((void**)&Wvfd, g_Wvf);
    cudaGetSymbolAddress((void**)&Wofd, g_Wof);
    cudaGetSymbolAddress((void**)&Q2d, g_Q2f);
    cudaGetSymbolAddress((void**)&K2d, g_K2f);
    cudaGetSymbolAddress((void**)&Vfd, g_Vf);

    cudaFuncSetAttribute(gemm_qkv, cudaFuncAttributeMaxDynamicSharedMemorySize, GSMEM);
    cudaFuncSetAttribute(gemm_f16o, cudaFuncAttributeMaxDynamicSharedMemorySize, GSMEM);
    cudaFuncSetAttribute(flash2, cudaFuncAttributeMaxDynamicSharedMemorySize, FSMEM);

    const int xt4 = S_LEN * 1024;
    const int wt4 = HDIM * 1024;
    conv_f16<<<(xt4 + 511) / 512, 256>>>(X, Xfd, xt4);
    conv_f16<<<(wt4 + 511) / 512, 256>>>(Wq, Wqfd, wt4);
    conv_f16<<<(wt4 + 511) / 512, 256>>>(Wk, Wkfd, wt4);
    conv_f16<<<(wt4 + 511) / 512, 256>>>(Wv, Wvfd, wt4);
    conv_f16<<<(wt4 + 511) / 512, 256>>>(Wo, Wofd, wt4);

    // Merged Q+K+V projection: 1536 CTAs, all plain fp16
    gemm_qkv<<<dim3(3 * HDIM / BN, S_LEN / BM), 128, GSMEM>>>(
        Xfd, Wqfd, Wkfd, Wvfd, Qhd, Khd, Vfd);

    rope_f16<<<(S_LEN * NHEADS * 16) / 256, 256>>>(Qhd, Khd, pos, Q2d, K2d);

    flash2<<<dim3(NHEADS, S_LEN / 64), 256, FSMEM>>>(Q2d, K2d, Vfd, Xfd);

    gemm_f16o<<<dim3(HDIM / BN, S_LEN / BM), 128, GSMEM>>>(Xfd, Wofd, out);
}